// round 13
// baseline (speedup 1.0000x reference)
#include <cuda_runtime.h>

// ComposeTransform: out[b] = trilinear(disp1[b], grid + disp2[b]) + disp2[b]
// vol per batch: [D,H,W,3], D=160, H=192, W=160, batch=2.
//
// 6 lanes per voxel: lane = (local_voxel lv=lane/6, sub=lane%6) where
// sub = z_half*3 + channel. All 6 lanes of a voxel gather from the SAME
// corner row per LDG instruction; their addresses are 6 consecutive floats
// (24B, one L1 line) -> the z-pair corners coalesce into ONE wavefront,
// halving gather line-touches vs one-LDG-per-corner.

#define DD 160
#define HH 192
#define WW 160
#define VOX (DD * HH * WW)
#define NVOX (2 * VOX)        // 9,830,400 voxels, = 40 * 245,760

__global__ __launch_bounds__(256, 8)
void compose_kernel(const float* __restrict__ d1,
                    const float* __restrict__ d2,
                    float* __restrict__ out)
{
    const int lane  = threadIdx.x & 31;
    const int gwarp = (blockIdx.x * blockDim.x + threadIdx.x) >> 5;

    int lv  = lane / 6;                 // local voxel 0..4 (5 for lanes 30,31)
    const int sub = lane - lv * 6;      // 0..5
    if (lv > 4) lv = 4;                 // keep lanes 30,31 address-safe
    const int zh  = sub >= 3 ? 1 : 0;   // z half: 0=floor, 1=ceil
    const int ch  = sub - zh * 3;       // channel 0..2

    const int v0 = gwarp * 5;           // first voxel of this warp
    const int v  = v0 + lv;             // this lane's voxel (global)

    // ---- d2: 15 contiguous floats per warp, loaded by lanes with sub<3 ----
    float e = 0.0f;
    if (lane < 30 && sub < 3) e = __ldg(d2 + (size_t)v * 3 + sub);
    const int lbase = lv * 6;
    float dx = __shfl_sync(0xffffffffu, e, lbase + 0);
    float dy = __shfl_sync(0xffffffffu, e, lbase + 1);
    float dz = __shfl_sync(0xffffffffu, e, lbase + 2);

    // ---- coordinates ----
    const int b = v / VOX;
    int r = v - b * VOX;
    int x = r / (HH * WW);
    int rem = r - x * (HH * WW);
    int y = rem / WW;
    int z = rem - y * WW;

    float lx = (float)x + dx;
    float ly = (float)y + dy;
    float lz = (float)z + dz;

    float fx = floorf(lx);
    float fy = floorf(ly);
    float fz = floorf(lz);

    // clipped floor / ceil corners (reference semantics)
    float i0x = fminf(fmaxf(fx, 0.0f), (float)(DD - 1));
    float i0y = fminf(fmaxf(fy, 0.0f), (float)(HH - 1));
    float i0z = fminf(fmaxf(fz, 0.0f), (float)(WW - 1));
    float i1x = fminf(fmaxf(fx + 1.0f, 0.0f), (float)(DD - 1));
    float i1y = fminf(fmaxf(fy + 1.0f, 0.0f), (float)(HH - 1));
    float i1z = fminf(fmaxf(fz + 1.0f, 0.0f), (float)(WW - 1));

    // weight attached to floor corner = clip(ceil_clipped - loc, 0, 1)
    float wfx = fminf(fmaxf(i1x - lx, 0.0f), 1.0f);
    float wfy = fminf(fmaxf(i1y - ly, 0.0f), 1.0f);
    float wfz = fminf(fmaxf(i1z - lz, 0.0f), 1.0f);
    float wcx = 1.0f - wfx;
    float wcy = 1.0f - wfy;
    float wcz = 1.0f - wfz;

    int ix0 = (int)i0x, iy0 = (int)i0y, iz0 = (int)i0z;
    int ix1 = (int)i1x, iy1 = (int)i1y, iz1 = (int)i1z;

    // this lane's z index and z weight
    const int   izs = zh ? iz1 : iz0;
    const float wz  = zh ? wcz : wfz;

    const float* vbase = d1 + (size_t)b * (size_t)(VOX * 3);

    // 4 corner rows (shared by all 6 lanes of the voxel)
    int off00 = ((ix0 * HH + iy0) * WW + izs) * 3 + ch;
    int off01 = ((ix0 * HH + iy1) * WW + izs) * 3 + ch;
    int off10 = ((ix1 * HH + iy0) * WW + izs) * 3 + ch;
    int off11 = ((ix1 * HH + iy1) * WW + izs) * 3 + ch;

    float w00 = wfx * wfy * wz;
    float w01 = wfx * wcy * wz;
    float w10 = wcx * wfy * wz;
    float w11 = wcx * wcy * wz;

    // 4 gather LDGs; per instruction the voxel's 6 lanes hit one 24B segment
    float g0 = __ldg(vbase + off00);
    float g1 = __ldg(vbase + off01);
    float g2 = __ldg(vbase + off10);
    float g3 = __ldg(vbase + off11);

    float acc = fmaf(w01, g1, w00 * g0) + fmaf(w11, g3, w10 * g2);

    // combine z halves: lane sub (<3) += lane sub+3
    float other = __shfl_down_sync(0xffffffffu, acc, 3);

    if (lane < 30 && sub < 3) {
        // e is exactly this element's d2 component; streaming store
        __stcs(out + (size_t)v * 3 + sub, acc + other + e);
    }
}

extern "C" void kernel_launch(void* const* d_in, const int* in_sizes, int n_in,
                              void* d_out, int out_size) {
    const float* d1 = (const float*)d_in[0];
    const float* d2 = (const float*)d_in[1];
    float* out = (float*)d_out;
    // 9,830,400 voxels / 5 per warp = 1,966,080 warps / 8 = 245,760 blocks
    int blocks = NVOX / 40;   // exact
    compose_kernel<<<blocks, 256>>>(d1, d2, out);
}

// round 14
// speedup vs baseline: 1.7604x; 1.7604x over previous
#include <cuda_runtime.h>

// ComposeTransform: out[b] = trilinear(disp1[b], grid + disp2[b]) + disp2[b]
// vol per batch: [D,H,W,3], D=160, H=192, W=160, batch=2.
// R10 skeleton (thread=(voxel,channel), AoS gathers, __stcs stores) with two
// sequential elements per thread (t and t+NELEM/2): halves block-wave churn
// while keeping sequential block->address locality within each half.

#define DD 160
#define HH 192
#define WW 160
#define VOX (DD * HH * WW)
#define NELEM (2 * VOX * 3)     // 29,491,200
#define HALF (NELEM / 2)        // 14,745,600 = 256 * 57,600

__device__ __forceinline__ float compose_one(const float* __restrict__ d1,
                                             const float* __restrict__ d2,
                                             int t)
{
    int v  = t / 3;          // voxel index (global, includes batch)
    int ch = t - v * 3;      // channel 0..2

    int b = v / VOX;
    int r = v - b * VOX;
    int x = r / (HH * WW);
    int rem = r - x * (HH * WW);
    int y = rem / WW;
    int z = rem - y * WW;

    const float* pd2 = d2 + (size_t)v * 3;
    float dx = __ldg(pd2 + 0);
    float dy = __ldg(pd2 + 1);
    float dz = __ldg(pd2 + 2);

    float lx = (float)x + dx;
    float ly = (float)y + dy;
    float lz = (float)z + dz;

    float fx = floorf(lx);
    float fy = floorf(ly);
    float fz = floorf(lz);

    // clipped floor / ceil corners (reference semantics)
    float i0x = fminf(fmaxf(fx, 0.0f), (float)(DD - 1));
    float i0y = fminf(fmaxf(fy, 0.0f), (float)(HH - 1));
    float i0z = fminf(fmaxf(fz, 0.0f), (float)(WW - 1));
    float i1x = fminf(fmaxf(fx + 1.0f, 0.0f), (float)(DD - 1));
    float i1y = fminf(fmaxf(fy + 1.0f, 0.0f), (float)(HH - 1));
    float i1z = fminf(fmaxf(fz + 1.0f, 0.0f), (float)(WW - 1));

    // weight attached to floor corner = clip(ceil_clipped - loc, 0, 1)
    float wfx = fminf(fmaxf(i1x - lx, 0.0f), 1.0f);
    float wfy = fminf(fmaxf(i1y - ly, 0.0f), 1.0f);
    float wfz = fminf(fmaxf(i1z - lz, 0.0f), 1.0f);
    float wcx = 1.0f - wfx;
    float wcy = 1.0f - wfy;
    float wcz = 1.0f - wfz;

    int ix0 = (int)i0x, iy0 = (int)i0y, iz0 = (int)i0z;
    int ix1 = (int)i1x, iy1 = (int)i1y, iz1 = (int)i1z;

    const float* vbase = d1 + (size_t)b * (size_t)(VOX * 3) + ch;

    int row00 = (ix0 * HH + iy0) * (WW * 3);
    int row01 = (ix0 * HH + iy1) * (WW * 3);
    int row10 = (ix1 * HH + iy0) * (WW * 3);
    int row11 = (ix1 * HH + iy1) * (WW * 3);
    int z0 = iz0 * 3;
    int z1 = iz1 * 3;

    float w00z0 = wfx * wfy * wfz;
    float w00z1 = wfx * wfy * wcz;
    float w01z0 = wfx * wcy * wfz;
    float w01z1 = wfx * wcy * wcz;
    float w10z0 = wcx * wfy * wfz;
    float w10z1 = wcx * wfy * wcz;
    float w11z0 = wcx * wcy * wfz;
    float w11z1 = wcx * wcy * wcz;

    float g0 = __ldg(vbase + (row00 + z0));
    float g1 = __ldg(vbase + (row00 + z1));
    float g2 = __ldg(vbase + (row01 + z0));
    float g3 = __ldg(vbase + (row01 + z1));
    float g4 = __ldg(vbase + (row10 + z0));
    float g5 = __ldg(vbase + (row10 + z1));
    float g6 = __ldg(vbase + (row11 + z0));
    float g7 = __ldg(vbase + (row11 + z1));

    float q0 = fmaf(w00z1, g1, w00z0 * g0);
    float q1 = fmaf(w01z1, g3, w01z0 * g2);
    float q2 = fmaf(w10z1, g5, w10z0 * g4);
    float q3 = fmaf(w11z1, g7, w11z0 * g6);
    float acc = (q0 + q1) + (q2 + q3);

    float d2c = (ch == 0) ? dx : ((ch == 1) ? dy : dz);
    return acc + d2c;
}

__global__ __launch_bounds__(256, 8)
void compose_kernel(const float* __restrict__ d1,
                    const float* __restrict__ d2,
                    float* __restrict__ out)
{
    int t = blockIdx.x * blockDim.x + threadIdx.x;   // 0 .. HALF-1, exact grid

    // first half
    __stcs(out + t, compose_one(d1, d2, t));
    // second half (sequential: registers reused, stays ~32 regs)
    int t2 = t + HALF;
    __stcs(out + t2, compose_one(d1, d2, t2));
}

extern "C" void kernel_launch(void* const* d_in, const int* in_sizes, int n_in,
                              void* d_out, int out_size) {
    const float* d1 = (const float*)d_in[0];
    const float* d2 = (const float*)d_in[1];
    float* out = (float*)d_out;
    // HALF = 14,745,600 = 256 * 57,600 exactly
    compose_kernel<<<HALF / 256, 256>>>(d1, d2, out);
}

// round 15
// speedup vs baseline: 1.7878x; 1.0156x over previous
#include <cuda_runtime.h>

// ComposeTransform: out[b] = trilinear(disp1[b], grid + disp2[b]) + disp2[b]
// vol per batch: [D,H,W,3], D=160, H=192, W=160, batch=2.
// R10/R14 skeleton (thread=(voxel,channel), AoS gathers, __stcs stores) with
// FOUR sequential elements per thread (t, t+Q, t+2Q, t+3Q): quarters the
// block count -> fewer block waves -> higher average occupancy, while each
// quarter keeps sequential block->address locality.

#define DD 160
#define HH 192
#define WW 160
#define VOX (DD * HH * WW)
#define NELEM (2 * VOX * 3)     // 29,491,200
#define QTR (NELEM / 4)         // 7,372,800 = 256 * 28,800

__device__ __forceinline__ float compose_one(const float* __restrict__ d1,
                                             const float* __restrict__ d2,
                                             int t)
{
    int v  = t / 3;          // voxel index (global, includes batch)
    int ch = t - v * 3;      // channel 0..2

    int b = v / VOX;
    int r = v - b * VOX;
    int x = r / (HH * WW);
    int rem = r - x * (HH * WW);
    int y = rem / WW;
    int z = rem - y * WW;

    const float* pd2 = d2 + (size_t)v * 3;
    float dx = __ldg(pd2 + 0);
    float dy = __ldg(pd2 + 1);
    float dz = __ldg(pd2 + 2);

    float lx = (float)x + dx;
    float ly = (float)y + dy;
    float lz = (float)z + dz;

    float fx = floorf(lx);
    float fy = floorf(ly);
    float fz = floorf(lz);

    // clipped floor / ceil corners (reference semantics)
    float i0x = fminf(fmaxf(fx, 0.0f), (float)(DD - 1));
    float i0y = fminf(fmaxf(fy, 0.0f), (float)(HH - 1));
    float i0z = fminf(fmaxf(fz, 0.0f), (float)(WW - 1));
    float i1x = fminf(fmaxf(fx + 1.0f, 0.0f), (float)(DD - 1));
    float i1y = fminf(fmaxf(fy + 1.0f, 0.0f), (float)(HH - 1));
    float i1z = fminf(fmaxf(fz + 1.0f, 0.0f), (float)(WW - 1));

    // weight attached to floor corner = clip(ceil_clipped - loc, 0, 1)
    float wfx = fminf(fmaxf(i1x - lx, 0.0f), 1.0f);
    float wfy = fminf(fmaxf(i1y - ly, 0.0f), 1.0f);
    float wfz = fminf(fmaxf(i1z - lz, 0.0f), 1.0f);
    float wcx = 1.0f - wfx;
    float wcy = 1.0f - wfy;
    float wcz = 1.0f - wfz;

    int ix0 = (int)i0x, iy0 = (int)i0y, iz0 = (int)i0z;
    int ix1 = (int)i1x, iy1 = (int)i1y, iz1 = (int)i1z;

    const float* vbase = d1 + (size_t)b * (size_t)(VOX * 3) + ch;

    int row00 = (ix0 * HH + iy0) * (WW * 3);
    int row01 = (ix0 * HH + iy1) * (WW * 3);
    int row10 = (ix1 * HH + iy0) * (WW * 3);
    int row11 = (ix1 * HH + iy1) * (WW * 3);
    int z0 = iz0 * 3;
    int z1 = iz1 * 3;

    float w00z0 = wfx * wfy * wfz;
    float w00z1 = wfx * wfy * wcz;
    float w01z0 = wfx * wcy * wfz;
    float w01z1 = wfx * wcy * wcz;
    float w10z0 = wcx * wfy * wfz;
    float w10z1 = wcx * wfy * wcz;
    float w11z0 = wcx * wcy * wfz;
    float w11z1 = wcx * wcy * wcz;

    float g0 = __ldg(vbase + (row00 + z0));
    float g1 = __ldg(vbase + (row00 + z1));
    float g2 = __ldg(vbase + (row01 + z0));
    float g3 = __ldg(vbase + (row01 + z1));
    float g4 = __ldg(vbase + (row10 + z0));
    float g5 = __ldg(vbase + (row10 + z1));
    float g6 = __ldg(vbase + (row11 + z0));
    float g7 = __ldg(vbase + (row11 + z1));

    float q0 = fmaf(w00z1, g1, w00z0 * g0);
    float q1 = fmaf(w01z1, g3, w01z0 * g2);
    float q2 = fmaf(w10z1, g5, w10z0 * g4);
    float q3 = fmaf(w11z1, g7, w11z0 * g6);
    float acc = (q0 + q1) + (q2 + q3);

    float d2c = (ch == 0) ? dx : ((ch == 1) ? dy : dz);
    return acc + d2c;
}

__global__ __launch_bounds__(256, 8)
void compose_kernel(const float* __restrict__ d1,
                    const float* __restrict__ d2,
                    float* __restrict__ out)
{
    int t = blockIdx.x * blockDim.x + threadIdx.x;   // 0 .. QTR-1, exact grid

    __stcs(out + t,            compose_one(d1, d2, t));
    __stcs(out + t + QTR,      compose_one(d1, d2, t + QTR));
    __stcs(out + t + 2 * QTR,  compose_one(d1, d2, t + 2 * QTR));
    __stcs(out + t + 3 * QTR,  compose_one(d1, d2, t + 3 * QTR));
}

extern "C" void kernel_launch(void* const* d_in, const int* in_sizes, int n_in,
                              void* d_out, int out_size) {
    const float* d1 = (const float*)d_in[0];
    const float* d2 = (const float*)d_in[1];
    float* out = (float*)d_out;
    // QTR = 7,372,800 = 256 * 28,800 exactly
    compose_kernel<<<QTR / 256, 256>>>(d1, d2, out);
}